// round 6
// baseline (speedup 1.0000x reference)
#include <cuda_runtime.h>
#include <cuda_bf16.h>

// ---------------- problem constants ----------------
#define BATCH   4
#define NPTS    32768
#define NCLS    3
#define KSEL    4096          // NMS_PRE_MAXSIZE
#define KPOST   512           // NMS_POST_MAXSIZE
#define NWORDS  64            // 4096 / 64
#define NW1     16            // stage-0: first 1024 boxes
#define NBUCK   65536         // 16-bit score-radix buckets
#define NCOPY   4             // histogram copies (atomic de-contention)

#define ROIS_ELEMS   (BATCH * KPOST * 7)          // 14336
#define SC_OFF       (ROIS_ELEMS)                 // 14336
#define LB_OFF       (ROIS_ELEMS + BATCH * KPOST) // 16384

// transposed bucket layout: thread t of 1024 owns value-buckets [t*64,t*64+64)
// at memory indices k*1024+t  (coalesced across t for fixed k)
#define MIDX(u) ((((u) & 63) << 10) | ((u) >> 6))

// ---------------- device scratch (no allocations allowed) ----------------
__device__ int                g_hist4[NCOPY][BATCH][NBUCK]; // 4 MB (zeroed by tail kernel)
__device__ int                g_histsum[BATCH][NBUCK];      // 1 MB
__device__ int                g_base[BATCH][NBUCK];         // 1 MB
__device__ int                g_basedyn[BATCH][NBUCK];      // 1 MB
__device__ int                g_candcnt[BATCH];
__device__ unsigned long long g_keyfull[BATCH][NPTS];       // 1 MB
__device__ unsigned long long g_cand[BATCH][NPTS];          // 1 MB

__device__ float4             g_box4[BATCH][KSEL];
__device__ float              g_area[BATCH][KSEL];
__device__ float              g_rois[BATCH][KSEL][7];
__device__ float              g_scores[BATCH][KSEL];
__device__ unsigned char      g_labels[BATCH][KSEL];

// ---------------- helpers ----------------
__device__ __forceinline__ unsigned f2ord(float s) {
    unsigned u = __float_as_uint(s);
    return (u & 0x80000000u) ? ~u : (u | 0x80000000u);
}

// exact-rounding IOU>thresh, identical op order to reference
__device__ __forceinline__ bool iou_gt(float4 A, float aA, float4 B, float aB) {
    float ix = __fsub_rn(fminf(A.z, B.z), fmaxf(A.x, B.x));
    float iy = __fsub_rn(fminf(A.w, B.w), fmaxf(A.y, B.y));
    if (ix > 0.0f && iy > 0.0f) {
        float inter = __fmul_rn(ix, iy);
        float denom = __fadd_rn(__fsub_rn(__fadd_rn(aA, aB), inter), 1e-6f);
        return __fdiv_rn(inter, denom) > 0.7f;
    }
    return false;
}

// ---------------- K1: keys + histogram (4 copies, transposed layout) ----------
__global__ void k_keys_hist(const float* __restrict__ cls) {
    int g = blockIdx.x * blockDim.x + threadIdx.x;      // 0 .. BATCH*NPTS-1
    if (g >= BATCH * NPTS) return;
    int b = g >> 15, i = g & (NPTS - 1);
    const float* cp = cls + (size_t)g * NCLS;
    float s = fmaxf(fmaxf(cp[0], cp[1]), cp[2]);
    unsigned u = f2ord(s);
    unsigned long long key = ((unsigned long long)u << 32) |
                             (unsigned long long)(0xFFFFFFFFu - (unsigned)i);
    g_keyfull[b][i] = key;
    atomicAdd(&g_hist4[blockIdx.x & (NCOPY - 1)][b][MIDX(u >> 16)], 1);
}

// ---------------- K2: sum copies + suffix-scan -> base (coalesced) -----------
__global__ void __launch_bounds__(1024)
k_scan_hist() {
    __shared__ int s[1024];
    __shared__ int smax;
    int b = blockIdx.x, t = threadIdx.x;
    if (t == 0) smax = 0;

    int h[64];
    int sum = 0;
#pragma unroll
    for (int k = 0; k < 64; k++) {
        int mi = k * 1024 + t;                       // coalesced across t
        int v = g_hist4[0][b][mi] + g_hist4[1][b][mi]
              + g_hist4[2][b][mi] + g_hist4[3][b][mi];
        h[k] = v; sum += v;
        g_histsum[b][mi] = v;
    }
    int own = sum;
    s[t] = sum;
    __syncthreads();
    for (int d = 1; d < 1024; d <<= 1) {             // inclusive suffix scan
        int v = (t + d < 1024) ? s[t + d] : 0;
        __syncthreads();
        s[t] += v;
        __syncthreads();
    }
    int run = s[t] - own;                            // strictly-above for bucket t*64+63
    int localmax = 0;
#pragma unroll
    for (int k = 63; k >= 0; k--) {
        int mi = k * 1024 + t;
        g_base[b][mi]    = run;
        g_basedyn[b][mi] = run;
        if (run < KSEL && h[k] > 0) {
            int e = run + h[k];
            if (e > localmax) localmax = e;
        }
        run += h[k];
    }
    if (localmax) atomicMax(&smax, localmax);
    __syncthreads();
    if (t == 0) g_candcnt[b] = smax;
}

// ---------------- K3: scatter candidates (cursor = basedyn) ------------------
__global__ void k_scatter() {
    int g = blockIdx.x * blockDim.x + threadIdx.x;
    if (g >= BATCH * NPTS) return;
    int b = g >> 15, i = g & (NPTS - 1);
    unsigned long long key = g_keyfull[b][i];
    int mi = MIDX((int)(key >> 48));
    if (g_base[b][mi] < KSEL) {
        int pos = atomicAdd(&g_basedyn[b][mi], 1);   // pos in [base, base+cnt) < NPTS
        g_cand[b][pos] = key;
    }
}

// ---------------- K4: exact rank + fused gather ------------------------------
__global__ void k_rankgather(const float* __restrict__ boxes,
                             const float* __restrict__ cls) {
    int g = blockIdx.x * blockDim.x + threadIdx.x;
    if (g >= BATCH * NPTS) return;
    int b = g >> 15, slot = g & (NPTS - 1);
    if (slot >= g_candcnt[b]) return;
    unsigned long long key = g_cand[b][slot];
    int mi = MIDX((int)(key >> 48));
    int segbase = g_base[b][mi];
    if (segbase >= KSEL) return;                     // stale-slot safety
    int segcnt  = g_histsum[b][mi];
    int rank = segbase;
    if (segcnt > 1) {
        const unsigned long long* seg = &g_cand[b][segbase];
        int gt = 0;
        for (int m = 0; m < segcnt; m++) gt += (__ldg(&seg[m]) > key);
        rank += gt;                                  // keys distinct -> unique ranks
    }
    if (rank >= KSEL) return;

    int idx = (int)(0xFFFFFFFFu - (unsigned)key);

    const float* bx = boxes + ((size_t)b * NPTS + idx) * 7;
    float v0 = bx[0], v1 = bx[1], v2 = bx[2], v3 = bx[3],
          v4 = bx[4], v5 = bx[5], v6 = bx[6];
    float* ro = &g_rois[b][rank][0];
    ro[0] = v0; ro[1] = v1; ro[2] = v2; ro[3] = v3;
    ro[4] = v4; ro[5] = v5; ro[6] = v6;

    const float* cp = cls + ((size_t)b * NPTS + idx) * NCLS;
    float c0 = cp[0], c1 = cp[1], c2 = cp[2];
    float s = c0; int lab = 0;
    if (c1 > s) { s = c1; lab = 1; }
    if (c2 > s) { s = c2; lab = 2; }
    g_scores[b][rank] = s;
    g_labels[b][rank] = (unsigned char)lab;

    float hx = __fmul_rn(0.5f, v3), hy = __fmul_rn(0.5f, v4);
    float x1 = __fsub_rn(v0, hx), x2 = __fadd_rn(v0, hx);
    float y1 = __fsub_rn(v1, hy), y2 = __fadd_rn(v1, hy);
    g_box4[b][rank] = make_float4(x1, y1, x2, y2);
    g_area[b][rank] = __fmul_rn(v3, v4);
}

// ---------------- K5: fused NMS (on-the-fly IOUs) + compact + state reset ----
// grid = BATCH, 1024 threads. Stage 0: greedy over first 1024 boxes with IOUs
// computed from smem. If >=512 survive (always, on sane data) -> compact + out.
// Else: full 4096-box fallback (correct by construction, never taken normally).
__global__ void __launch_bounds__(1024)
k_nms_out(float* __restrict__ out) {
    int b = blockIdx.x, tid = threadIdx.x;
    extern __shared__ unsigned char dsm[];
    float4* sbox  = (float4*)dsm;                    // up to 4096 * 16B
    float*  sarea = (float*)(dsm + KSEL * 16);       // up to 4096 * 4B

    __shared__ unsigned long long remv[NWORDS];
    __shared__ unsigned long long acc_s[NWORDS];
    __shared__ unsigned long long diag[64];
    __shared__ unsigned long long part[1088];        // stage0 r*17+cw ; fb q*65+c
    __shared__ unsigned long long red[4][16];
    __shared__ int pref[NWORDS];
    __shared__ int s_fb;

    // stage-0 boxes -> smem (first 1024)
    if (tid < NW1 * 64) {
        sbox[tid]  = g_box4[b][tid];
        sarea[tid] = g_area[b][tid];
    }
    if (tid < NWORDS) { remv[tid] = 0ull; acc_s[tid] = 0ull; }
    __syncthreads();

    // ---------- stage 0: 16 words, IOUs on the fly ----------
    int r = tid >> 4, cw = tid & 15;                 // row 0..63, col-word 0..15
    for (int w = 0; w < NW1; w++) {
        if (tid < 64) {                              // diagonal block
            int i = w * 64 + tid;
            float4 A = sbox[i]; float aA = sarea[i];
            unsigned long long d = 0ull;
            for (int j = tid + 1; j < 64; j++) {
                if (iou_gt(A, aA, sbox[w * 64 + j], sarea[w * 64 + j]))
                    d |= (1ull << j);
            }
            diag[tid] = d;
        }
        __syncthreads();
        if (tid == 0) {                              // serial greedy decisions
            unsigned long long rem = remv[w], acc = 0ull;
            unsigned long long dn = diag[0];
#pragma unroll
            for (int bit = 0; bit < 64; bit++) {
                unsigned long long d = dn;
                if (bit < 63) dn = diag[bit + 1];
                if (!((rem >> bit) & 1ull)) { acc |= (1ull << bit); rem |= d; }
            }
            acc_s[w] = acc;
        }
        __syncthreads();

        // row-OR: accepted rows of word w suppress into later words
        unsigned long long acc = acc_s[w];
        unsigned long long p = 0ull;
        if (cw > w && ((acc >> r) & 1ull)) {
            int i = w * 64 + r;
            float4 A = sbox[i]; float aA = sarea[i];
            for (int j = 0; j < 64; j++) {
                if (iou_gt(A, aA, sbox[cw * 64 + j], sarea[cw * 64 + j]))
                    p |= (1ull << j);
            }
        }
        part[r * 17 + cw] = p;
        __syncthreads();
        if (tid < 64) {
            int q = tid >> 4, c = tid & 15;
            unsigned long long v = 0ull;
#pragma unroll
            for (int k = 0; k < 16; k++) v |= part[(q * 16 + k) * 17 + c];
            red[q][c] = v;
        }
        __syncthreads();
        if (tid < 16)
            remv[tid] |= red[0][tid] | red[1][tid] | red[2][tid] | red[3][tid];
        __syncthreads();
    }

    if (tid == 0) {
        int cnt = 0;
        for (int w = 0; w < NW1; w++) cnt += __popcll(acc_s[w]);
        s_fb = (cnt < KPOST);
    }
    __syncthreads();

    // ---------- fallback: full 4096 (never taken on sane data) ----------
    if (s_fb) {
        for (int i = tid; i < KSEL; i += 1024) {
            sbox[i]  = g_box4[b][i];
            sarea[i] = g_area[b][i];
        }
        if (tid < NWORDS) remv[tid] = 0ull;
        __syncthreads();

        int qg = tid >> 6, colw = tid & 63;
        for (int w = 0; w < NWORDS; w++) {
            if (tid < 64) {
                int i = w * 64 + tid;
                float4 A = sbox[i]; float aA = sarea[i];
                unsigned long long d = 0ull;
                for (int j = tid + 1; j < 64; j++) {
                    if (iou_gt(A, aA, sbox[w * 64 + j], sarea[w * 64 + j]))
                        d |= (1ull << j);
                }
                diag[tid] = d;
            }
            __syncthreads();
            if (tid == 0) {
                unsigned long long rem = remv[w], acc = 0ull;
#pragma unroll
                for (int bit = 0; bit < 64; bit++) {
                    if (!((rem >> bit) & 1ull)) { acc |= (1ull << bit); rem |= diag[bit]; }
                }
                acc_s[w] = acc;
            }
            __syncthreads();

            unsigned long long acc = acc_s[w];
            unsigned long long p = 0ull;
            if (colw > w) {
#pragma unroll
                for (int rr = 0; rr < 4; rr++) {
                    int rbit = qg + rr * 16;
                    if ((acc >> rbit) & 1ull) {
                        int i = w * 64 + rbit;
                        float4 A = sbox[i]; float aA = sarea[i];
                        for (int j = 0; j < 64; j++) {
                            if (iou_gt(A, aA, sbox[colw * 64 + j], sarea[colw * 64 + j]))
                                p |= (1ull << j);
                        }
                    }
                }
            }
            part[qg * 65 + colw] = p;
            __syncthreads();
            if (tid < 64) {
                unsigned long long rr2 = remv[tid];
#pragma unroll
                for (int k = 0; k < 16; k++) rr2 |= part[k * 65 + tid];
                remv[tid] = rr2;
            }
            __syncthreads();
        }
    }

    // ---------- reset histogram copies for next replay ----------
    {
        int4 z = make_int4(0, 0, 0, 0);
#pragma unroll
        for (int c = 0; c < NCOPY; c++) {
            int4* h4 = (int4*)&g_hist4[c][b][0];
            for (int e = tid; e < NBUCK / 4; e += 1024) h4[e] = z;
        }
    }

    // ---------- compact + output (d_out poisoned -> zero slice first) ----------
    float* rbase = out + b * KPOST * 7;
    for (int e = tid; e < KPOST * 7; e += 1024) rbase[e] = 0.0f;
    if (tid < KPOST) {
        out[SC_OFF + b * KPOST + tid] = 0.0f;
        out[LB_OFF + b * KPOST + tid] = 0.0f;
    }
    if (tid == 0) {
        int s = 0;
        for (int w = 0; w < NWORDS; w++) { pref[w] = s; s += __popcll(acc_s[w]); }
    }
    __syncthreads();

    if (tid < NWORDS) {
        unsigned long long a = acc_s[tid];
        int rank = pref[tid];
        while (a && rank < KPOST) {
            int bit = __ffsll((long long)a) - 1;
            a &= a - 1;
            int i = tid * 64 + bit;
            const float* ro = &g_rois[b][i][0];
            int obase = (b * KPOST + rank) * 7;
#pragma unroll
            for (int c = 0; c < 7; c++) out[obase + c] = ro[c];
            out[SC_OFF + b * KPOST + rank] = g_scores[b][i];
            out[LB_OFF + b * KPOST + rank] = (float)(g_labels[b][i] + 1);
            rank++;
        }
    }
}

// ---------------- launch (5 kernels) ----------------
extern "C" void kernel_launch(void* const* d_in, const int* in_sizes, int n_in,
                              void* d_out, int out_size) {
    const float* boxes = (const float*)d_in[0];
    const float* cls   = (const float*)d_in[1];
    if (n_in >= 2 && in_sizes[0] == BATCH * NPTS * NCLS) {
        boxes = (const float*)d_in[1];
        cls   = (const float*)d_in[0];
    }
    float* out = (float*)d_out;

    const int NTOT = BATCH * NPTS;
    const int DSM  = KSEL * 16 + KSEL * 4;           // 80 KB (fallback boxes)

    static int smem_set = 0;
    if (!smem_set) {
        cudaFuncSetAttribute(k_nms_out,
                             cudaFuncAttributeMaxDynamicSharedMemorySize, DSM);
        smem_set = 1;
    }

    k_keys_hist<<<NTOT / 256, 256>>>(cls);
    k_scan_hist<<<BATCH, 1024>>>();
    k_scatter<<<NTOT / 256, 256>>>();
    k_rankgather<<<NTOT / 256, 256>>>(boxes, cls);
    k_nms_out<<<BATCH, 1024, DSM>>>(out);
}

// round 7
// speedup vs baseline: 2.1854x; 2.1854x over previous
#include <cuda_runtime.h>
#include <cuda_bf16.h>

// ---------------- problem constants ----------------
#define BATCH   4
#define NPTS    32768
#define NCLS    3
#define KSEL    4096          // NMS_PRE_MAXSIZE
#define KPOST   512           // NMS_POST_MAXSIZE
#define NWORDS  64            // 4096 / 64
#define NW1     16            // stage-0: first 1024 boxes
#define NBUCK   65536         // 16-bit score-radix buckets

#define ROIS_ELEMS   (BATCH * KPOST * 7)          // 14336
#define SC_OFF       (ROIS_ELEMS)                 // 14336
#define LB_OFF       (ROIS_ELEMS + BATCH * KPOST) // 16384

// ---------------- device scratch (no allocations allowed) ----------------
__device__ int                g_hist[BATCH][NBUCK];         // 1 MB (self-zeroed by k_scan_hist)
__device__ int                g_base[BATCH][NBUCK];         // 1 MB (static suffix counts)
__device__ int                g_basedyn[BATCH][NBUCK];      // 1 MB (scatter cursors)
__device__ int                g_candcnt[BATCH];
__device__ unsigned long long g_keyfull[BATCH][NPTS];       // 1 MB
__device__ unsigned long long g_cand[BATCH][NPTS];          // 1 MB (bucket-grouped)

__device__ float4             g_box4[BATCH][KSEL];
__device__ float              g_area[BATCH][KSEL];
__device__ float              g_rois[BATCH][KSEL][7];
__device__ float              g_scores[BATCH][KSEL];
__device__ unsigned char      g_labels[BATCH][KSEL];
__device__ unsigned long long g_mask0[BATCH][1024 * NW1];   // 512 KB, [row][word16]
__device__ unsigned long long g_accept[BATCH][NWORDS];

// ---------------- helpers ----------------
__device__ __forceinline__ unsigned f2ord(float s) {
    unsigned u = __float_as_uint(s);
    return (u & 0x80000000u) ? ~u : (u | 0x80000000u);
}

// exact-rounding IOU>thresh, identical op order to reference
__device__ __forceinline__ bool iou_gt(float4 A, float aA, float4 B, float aB) {
    float ix = __fsub_rn(fminf(A.z, B.z), fmaxf(A.x, B.x));
    float iy = __fsub_rn(fminf(A.w, B.w), fmaxf(A.y, B.y));
    if (ix > 0.0f && iy > 0.0f) {
        float inter = __fmul_rn(ix, iy);
        float denom = __fadd_rn(__fsub_rn(__fadd_rn(aA, aB), inter), 1e-6f);
        return __fdiv_rn(inter, denom) > 0.7f;
    }
    return false;
}

// ---------------- K1: keys + 16-bit bucket histogram ----------------
__global__ void k_keys_hist(const float* __restrict__ cls) {
    int g = blockIdx.x * blockDim.x + threadIdx.x;      // 0 .. BATCH*NPTS-1
    if (g >= BATCH * NPTS) return;
    int b = g >> 15, i = g & (NPTS - 1);
    const float* cp = cls + (size_t)g * NCLS;
    float s = fmaxf(fmaxf(cp[0], cp[1]), cp[2]);
    unsigned u = f2ord(s);
    unsigned long long key = ((unsigned long long)u << 32) |
                             (unsigned long long)(0xFFFFFFFFu - (unsigned)i);
    g_keyfull[b][i] = key;
    atomicAdd(&g_hist[b][u >> 16], 1);
}

// ---------------- K2: suffix-scan -> base, basedyn, candcnt; self-zero hist --
__global__ void __launch_bounds__(1024)
k_scan_hist() {
    __shared__ int s[1024];
    __shared__ int smax;
    int b = blockIdx.x, t = threadIdx.x;
    if (t == 0) smax = 0;

    int h[64];
    int sum = 0;
    const int b0 = t * 64;
#pragma unroll
    for (int k = 0; k < 64; k++) { h[k] = g_hist[b][b0 + k]; sum += h[k]; }
    int own = sum;
    s[t] = sum;
    __syncthreads();
    for (int d = 1; d < 1024; d <<= 1) {             // inclusive suffix scan
        int v = (t + d < 1024) ? s[t + d] : 0;
        __syncthreads();
        s[t] += v;
        __syncthreads();
    }
    int run = s[t] - own;                            // strictly-above for bucket b0+63
    int localmax = 0;
#pragma unroll
    for (int k = 63; k >= 0; k--) {
        g_base[b][b0 + k]    = run;
        g_basedyn[b][b0 + k] = run;                  // scatter cursor starts at base
        if (run < KSEL && h[k] > 0) {
            int e = run + h[k];
            if (e > localmax) localmax = e;
        }
        run += h[k];
    }
    if (localmax) atomicMax(&smax, localmax);
    // zero the histogram for the next replay (coalesced; safe: all reads done
    // before the scan-loop barriers above)
#pragma unroll
    for (int k = 0; k < 64; k++) g_hist[b][k * 1024 + t] = 0;
    __syncthreads();
    if (t == 0) g_candcnt[b] = smax;
}

// ---------------- K3: scatter candidates (cursor = basedyn) ------------------
__global__ void k_scatter() {
    int g = blockIdx.x * blockDim.x + threadIdx.x;
    if (g >= BATCH * NPTS) return;
    int b = g >> 15, i = g & (NPTS - 1);
    unsigned long long key = g_keyfull[b][i];
    int bucket = (int)(key >> 48);
    if (g_base[b][bucket] < KSEL) {
        int pos = atomicAdd(&g_basedyn[b][bucket], 1);  // pos in [base, base+cnt) < NPTS
        g_cand[b][pos] = key;
    }
}

// ---------------- K4: exact rank + fused gather ------------------------------
__global__ void k_rankgather(const float* __restrict__ boxes,
                             const float* __restrict__ cls) {
    int g = blockIdx.x * blockDim.x + threadIdx.x;
    if (g >= BATCH * NPTS) return;
    int b = g >> 15, slot = g & (NPTS - 1);
    if (slot >= g_candcnt[b]) return;
    unsigned long long key = g_cand[b][slot];
    int bucket = (int)(key >> 48);
    int segbase = g_base[b][bucket];
    if (segbase >= KSEL) return;                     // stale-slot safety
    // segcnt = (# > bucket-1) - (# > bucket) = hist[bucket]
    int segcnt = ((bucket > 0) ? g_base[b][bucket - 1] : NPTS) - segbase;
    int rank = segbase;
    if (segcnt > 1) {
        const unsigned long long* seg = &g_cand[b][segbase];
        int gt = 0;
        for (int m = 0; m < segcnt; m++) gt += (__ldg(&seg[m]) > key);
        rank += gt;                                  // keys distinct -> unique ranks
    }
    if (rank >= KSEL) return;

    int idx = (int)(0xFFFFFFFFu - (unsigned)key);

    const float* bx = boxes + ((size_t)b * NPTS + idx) * 7;
    float v0 = bx[0], v1 = bx[1], v2 = bx[2], v3 = bx[3],
          v4 = bx[4], v5 = bx[5], v6 = bx[6];
    float* ro = &g_rois[b][rank][0];
    ro[0] = v0; ro[1] = v1; ro[2] = v2; ro[3] = v3;
    ro[4] = v4; ro[5] = v5; ro[6] = v6;

    const float* cp = cls + ((size_t)b * NPTS + idx) * NCLS;
    float c0 = cp[0], c1 = cp[1], c2 = cp[2];
    float s = c0; int lab = 0;
    if (c1 > s) { s = c1; lab = 1; }
    if (c2 > s) { s = c2; lab = 2; }
    g_scores[b][rank] = s;
    g_labels[b][rank] = (unsigned char)lab;

    float hx = __fmul_rn(0.5f, v3), hy = __fmul_rn(0.5f, v4);
    float x1 = __fsub_rn(v0, hx), x2 = __fadd_rn(v0, hx);
    float y1 = __fsub_rn(v1, hy), y2 = __fadd_rn(v1, hy);
    g_box4[b][rank] = make_float4(x1, y1, x2, y2);
    g_area[b][rank] = __fmul_rn(v3, v4);
}

// ---------------- K5: stage-0 suppression mask (broadcast smem, 256+ CTAs) ---
__global__ void __launch_bounds__(64)
k_mask0() {
    int cb = blockIdx.x, rb = blockIdx.y, b = blockIdx.z;
    if (cb < rb) return;

    __shared__ float4 sb[64];
    __shared__ float  sa[64];
    int t = threadIdx.x;
    sb[t] = g_box4[b][cb * 64 + t];
    sa[t] = g_area[b][cb * 64 + t];
    __syncthreads();

    int i = rb * 64 + t;
    float4 me = g_box4[b][i];
    float  a  = g_area[b][i];
    unsigned long long m = 0;
    int j0 = (cb == rb) ? (t + 1) : 0;               // only j > i suppressed
    for (int jj = j0; jj < 64; jj++) {               // sb[jj]: broadcast, conflict-free
        if (iou_gt(me, a, sb[jj], sa[jj])) m |= (1ull << jj);
    }
    g_mask0[b][(size_t)i * NW1 + cb] = m;
}

// ---------------- K6: scan stage-0 (mask loads) + never-taken full fallback --
__global__ void __launch_bounds__(1024)
k_scan(float unused) {
    int b = blockIdx.x, tid = threadIdx.x;
    extern __shared__ unsigned char dsm[];
    float4* sbox  = (float4*)dsm;                    // fallback only: 4096*16B
    float*  sarea = (float*)(dsm + KSEL * 16);       // fallback only: 4096*4B

    __shared__ unsigned long long remv[NWORDS];
    __shared__ unsigned long long acc_s[NWORDS];
    __shared__ unsigned long long diag[64];
    __shared__ unsigned long long part[1088];        // stage0 r*17+cw ; fb q*65+c
    __shared__ unsigned long long red[4][16];
    __shared__ int s_fb;

    if (tid < NWORDS) { remv[tid] = 0ull; acc_s[tid] = 0ull; }
    __syncthreads();

    // ---------- stage 0: load 64x16 mask block per word, pipelined ----------
    const unsigned long long* M0 = g_mask0[b];
    int r = tid >> 4, cw = tid & 15;                 // row 0..63, col-word 0..15
    unsigned long long m = M0[(size_t)r * NW1 + cw]; // word-0 block (coalesced)

    for (int w = 0; w < NW1; w++) {
        if (cw == w) diag[r] = m;                    // diagonal for free
        __syncthreads();
        if (tid == 0) {                              // serial greedy decisions
            unsigned long long rem = remv[w], acc = 0ull;
            unsigned long long dn = diag[0];
#pragma unroll
            for (int bit = 0; bit < 64; bit++) {
                unsigned long long d = dn;
                if (bit < 63) dn = diag[bit + 1];
                if (!((rem >> bit) & 1ull)) { acc |= (1ull << bit); rem |= d; }
            }
            acc_s[w] = acc;
        }
        // prefetch next word's block while greedy runs
        unsigned long long mn = 0ull;
        if (w + 1 < NW1) mn = M0[(size_t)((w + 1) * 64 + r) * NW1 + cw];
        __syncthreads();

        unsigned long long acc = acc_s[w];
        part[r * 17 + cw] = ((acc >> r) & 1ull) ? m : 0ull;
        __syncthreads();
        if (tid < 64) {
            int q = tid >> 4, c = tid & 15;
            unsigned long long v = 0ull;
#pragma unroll
            for (int k = 0; k < 16; k++) v |= part[(q * 16 + k) * 17 + c];
            red[q][c] = v;
        }
        __syncthreads();
        if (tid < 16)
            remv[tid] |= red[0][tid] | red[1][tid] | red[2][tid] | red[3][tid];
        __syncthreads();
        m = mn;
    }

    if (tid == 0) {
        int cnt = 0;
        for (int w = 0; w < NW1; w++) cnt += __popcll(acc_s[w]);
        s_fb = (cnt < KPOST);
    }
    __syncthreads();

    if (!s_fb) {
        if (tid < NWORDS) g_accept[b][tid] = acc_s[tid];   // words >=16 are 0
        return;
    }

    // ---------- fallback: full 4096 on-the-fly NMS (never taken normally) ----
    for (int i = tid; i < KSEL; i += 1024) {
        sbox[i]  = g_box4[b][i];
        sarea[i] = g_area[b][i];
    }
    if (tid < NWORDS) remv[tid] = 0ull;
    __syncthreads();

    int qg = tid >> 6, colw = tid & 63;
    for (int w = 0; w < NWORDS; w++) {
        if (tid < 64) {
            int i = w * 64 + tid;
            float4 A = sbox[i]; float aA = sarea[i];
            unsigned long long d = 0ull;
            for (int j = tid + 1; j < 64; j++) {
                if (iou_gt(A, aA, sbox[w * 64 + j], sarea[w * 64 + j]))
                    d |= (1ull << j);
            }
            diag[tid] = d;
        }
        __syncthreads();
        if (tid == 0) {
            unsigned long long rem = remv[w], acc = 0ull;
#pragma unroll
            for (int bit = 0; bit < 64; bit++) {
                if (!((rem >> bit) & 1ull)) { acc |= (1ull << bit); rem |= diag[bit]; }
            }
            acc_s[w] = acc;
        }
        __syncthreads();

        unsigned long long acc = acc_s[w];
        unsigned long long p = 0ull;
        if (colw > w) {
#pragma unroll
            for (int rr = 0; rr < 4; rr++) {
                int rbit = qg + rr * 16;
                if ((acc >> rbit) & 1ull) {
                    int i = w * 64 + rbit;
                    float4 A = sbox[i]; float aA = sarea[i];
                    for (int j = 0; j < 64; j++) {
                        if (iou_gt(A, aA, sbox[colw * 64 + j], sarea[colw * 64 + j]))
                            p |= (1ull << j);
                    }
                }
            }
        }
        part[qg * 65 + colw] = p;
        __syncthreads();
        if (tid < 64) {
            unsigned long long rr2 = remv[tid];
#pragma unroll
            for (int k = 0; k < 16; k++) rr2 |= part[k * 65 + tid];
            remv[tid] = rr2;
        }
        __syncthreads();
    }
    if (tid < NWORDS) g_accept[b][tid] = acc_s[tid];
}

// ---------------- K7: zero output slice + compact ----------------
__global__ void __launch_bounds__(512)
k_compact(float* __restrict__ out) {
    int b = blockIdx.x, t = threadIdx.x;

    float* rbase = out + b * KPOST * 7;              // d_out poisoned -> zero slice
    for (int e = t; e < KPOST * 7; e += 512) rbase[e] = 0.0f;
    if (t < KPOST) {
        out[SC_OFF + b * KPOST + t] = 0.0f;
        out[LB_OFF + b * KPOST + t] = 0.0f;
    }

    __shared__ unsigned long long acc[NWORDS];
    __shared__ int pref[NWORDS];
    if (t < NWORDS) acc[t] = g_accept[b][t];
    __syncthreads();
    if (t == 0) {
        int s = 0;
        for (int w = 0; w < NWORDS; w++) { pref[w] = s; s += __popcll(acc[w]); }
    }
    __syncthreads();

    if (t < NWORDS) {
        unsigned long long a = acc[t];
        int rank = pref[t];
        while (a && rank < KPOST) {
            int bit = __ffsll((long long)a) - 1;
            a &= a - 1;
            int i = t * 64 + bit;
            const float* ro = &g_rois[b][i][0];
            int obase = (b * KPOST + rank) * 7;
#pragma unroll
            for (int c = 0; c < 7; c++) out[obase + c] = ro[c];
            out[SC_OFF + b * KPOST + rank] = g_scores[b][i];
            out[LB_OFF + b * KPOST + rank] = (float)(g_labels[b][i] + 1);
            rank++;
        }
    }
}

// ---------------- launch (7 kernels) ----------------
extern "C" void kernel_launch(void* const* d_in, const int* in_sizes, int n_in,
                              void* d_out, int out_size) {
    const float* boxes = (const float*)d_in[0];
    const float* cls   = (const float*)d_in[1];
    if (n_in >= 2 && in_sizes[0] == BATCH * NPTS * NCLS) {
        boxes = (const float*)d_in[1];
        cls   = (const float*)d_in[0];
    }
    float* out = (float*)d_out;

    const int NTOT = BATCH * NPTS;
    const int DSM  = KSEL * 16 + KSEL * 4;           // 80 KB (fallback boxes)

    cudaFuncSetAttribute(k_scan,
                         cudaFuncAttributeMaxDynamicSharedMemorySize, DSM);

    k_keys_hist<<<NTOT / 256, 256>>>(cls);
    k_scan_hist<<<BATCH, 1024>>>();
    k_scatter<<<NTOT / 256, 256>>>();
    k_rankgather<<<NTOT / 256, 256>>>(boxes, cls);
    k_mask0<<<dim3(NW1, NW1, BATCH), 64>>>();
    k_scan<<<BATCH, 1024, DSM>>>(0.0f);
    k_compact<<<BATCH, 512>>>(out);
}

// round 9
// speedup vs baseline: 4.1990x; 1.9214x over previous
#include <cuda_runtime.h>
#include <cuda_bf16.h>

// ---------------- problem constants ----------------
#define BATCH   4
#define NPTS    32768
#define NCLS    3
#define KSEL    4096          // NMS_PRE_MAXSIZE
#define KPOST   512           // NMS_POST_MAXSIZE
#define NWORDS  64            // 4096 / 64
#define NW1     16            // stage-0: first 1024 boxes
#define NBUCK   4096          // fine monotone buckets
#define CAND_CAP 6144         // smem candidate staging capacity

#define ROIS_ELEMS   (BATCH * KPOST * 7)          // 14336
#define SC_OFF       (ROIS_ELEMS)                 // 14336
#define LB_OFF       (ROIS_ELEMS + BATCH * KPOST) // 16384

// ---------------- device scratch (no allocations allowed) ----------------
__device__ unsigned long long g_cand[BATCH][NPTS];          // overflow path only
__device__ float4             g_box4[BATCH][KSEL];          // x1,y1,x2,y2
__device__ float              g_area[BATCH][KSEL];
__device__ float              g_rois[BATCH][KSEL][7];
__device__ float              g_scores[BATCH][KSEL];
__device__ unsigned char      g_labels[BATCH][KSEL];
__device__ unsigned long long g_mask0[BATCH][1024 * NW1];   // 512 KB [row][word16]

// ---------------- helpers ----------------
__device__ __forceinline__ unsigned f2ord(float s) {
    unsigned u = __float_as_uint(s);
    return (u & 0x80000000u) ? ~u : (u | 0x80000000u);
}

// monotone (non-decreasing in u) 12-bit bucket; fine resolution for s>=0.5
__device__ __forceinline__ int bucket_of(unsigned u) {
    if (u >= 0xBF000000u) {
        unsigned f = 2048u + ((u - 0xBF000000u) >> 12);
        return (int)(f > 4095u ? 4095u : f);
    }
    return (int)(u >> 21);                           // <= 1528 < 2048, monotone
}

// exact-rounding IOU>thresh, identical op order to reference
__device__ __forceinline__ bool iou_gt(float4 A, float aA, float4 B, float aB) {
    float ix = __fsub_rn(fminf(A.z, B.z), fmaxf(A.x, B.x));
    float iy = __fsub_rn(fminf(A.w, B.w), fmaxf(A.y, B.y));
    if (ix > 0.0f && iy > 0.0f) {
        float inter = __fmul_rn(ix, iy);
        float denom = __fadd_rn(__fsub_rn(__fadd_rn(aA, aB), inter), 1e-6f);
        return __fdiv_rn(inter, denom) > 0.7f;
    }
    return false;
}

// ================= K1: fused top-k select (hist+scan+scatter+rank+gather) ====
// grid = BATCH, 1024 threads. All state in smem; no cross-replay globals.
__global__ void __launch_bounds__(1024)
k_select(const float* __restrict__ boxes, const float* __restrict__ cls) {
    extern __shared__ unsigned char dsm[];
    int* s_hist = (int*)dsm;                         // 4096 ints (also cursors)
    int* s_base = (int*)(dsm + 16384);               // 4096 ints
    unsigned long long* s_keys = (unsigned long long*)(dsm + 32768); // 6144 keys

    __shared__ int s_red[1024];
    __shared__ int s_max;

    int b = blockIdx.x, t = threadIdx.x;
    const float* cb  = cls   + (size_t)b * NPTS * NCLS;
    const float* bx0 = boxes + (size_t)b * NPTS * 7;

    for (int k = t; k < NBUCK; k += 1024) s_hist[k] = 0;
    if (t == 0) s_max = 0;
    __syncthreads();

    // ---- pass 1: histogram (smem atomics) ----
#pragma unroll 4
    for (int k = 0; k < 32; k++) {
        int i = k * 1024 + t;
        float c0 = cb[i * 3], c1 = cb[i * 3 + 1], c2 = cb[i * 3 + 2];
        float s = fmaxf(fmaxf(c0, c1), c2);
        atomicAdd(&s_hist[bucket_of(f2ord(s))], 1);
    }
    __syncthreads();

    // ---- suffix scan (thread owns 4 buckets) ----
    int h[4];
    int own = 0;
    const int b0 = t * 4;
#pragma unroll
    for (int k = 0; k < 4; k++) { h[k] = s_hist[b0 + k]; own += h[k]; }
    s_red[t] = own;
    __syncthreads();
    for (int d = 1; d < 1024; d <<= 1) {             // inclusive suffix scan
        int v = (t + d < 1024) ? s_red[t + d] : 0;
        __syncthreads();
        s_red[t] += v;
        __syncthreads();
    }
    int run = s_red[t] - own;                        // strictly-above for bucket b0+3
    int lmax = 0;
#pragma unroll
    for (int k = 3; k >= 0; k--) {
        s_base[b0 + k] = run;
        if (run < KSEL && h[k] > 0) {
            int e = run + h[k];
            if (e > lmax) lmax = e;
        }
        run += h[k];
    }
    if (lmax) atomicMax(&s_max, lmax);
    __syncthreads();

    const int candcnt = s_max;
    const int ovf = (candcnt > CAND_CAP);            // adversarial-data fallback
    unsigned long long* keys = ovf ? &g_cand[b][0] : s_keys;

    // cursors: reuse s_hist
    for (int k = t; k < NBUCK; k += 1024) s_hist[k] = s_base[k];
    __syncthreads();

    // ---- pass 2: scatter candidate keys, bucket-grouped ----
#pragma unroll 4
    for (int k = 0; k < 32; k++) {
        int i = k * 1024 + t;
        float c0 = cb[i * 3], c1 = cb[i * 3 + 1], c2 = cb[i * 3 + 2];
        float s = fmaxf(fmaxf(c0, c1), c2);
        unsigned u = f2ord(s);
        int bk = bucket_of(u);
        if (s_base[bk] < KSEL) {
            int pos = atomicAdd(&s_hist[bk], 1);     // pos in [base, base+cnt) <= candcnt
            keys[pos] = ((unsigned long long)u << 32) |
                        (unsigned long long)(0xFFFFFFFFu - (unsigned)i);
        }
    }
    __syncthreads();

    // ---- rank within segment + gather boxes ----
    for (int slot = t; slot < candcnt; slot += 1024) {
        unsigned long long key = keys[slot];
        unsigned u = (unsigned)(key >> 32);
        int bk = bucket_of(u);
        int segbase = s_base[bk];
        if (segbase >= KSEL) continue;               // safety
        int above = (bk > 0) ? s_base[bk - 1] : NPTS;
        int segcnt = above - segbase;
        int rank = segbase;
        if (segcnt > 1) {
            int gt = 0;
#pragma unroll 4
            for (int m = 0; m < segcnt; m++) gt += (keys[segbase + m] > key);
            rank += gt;                              // keys distinct -> unique ranks
        }
        if (rank >= KSEL) continue;

        int idx = (int)(0xFFFFFFFFu - (unsigned)key);
        const float* bx = bx0 + (size_t)idx * 7;
        float v0 = bx[0], v1 = bx[1], v2 = bx[2], v3 = bx[3],
              v4 = bx[4], v5 = bx[5], v6 = bx[6];
        float* ro = &g_rois[b][rank][0];
        ro[0] = v0; ro[1] = v1; ro[2] = v2; ro[3] = v3;
        ro[4] = v4; ro[5] = v5; ro[6] = v6;

        const float* cp = cb + (size_t)idx * NCLS;
        float c0 = cp[0], c1 = cp[1], c2 = cp[2];
        float s = c0; int lab = 0;
        if (c1 > s) { s = c1; lab = 1; }
        if (c2 > s) { s = c2; lab = 2; }
        g_scores[b][rank] = s;
        g_labels[b][rank] = (unsigned char)lab;

        // match reference rounding exactly (mul then sub/add, no FMA)
        float hx = __fmul_rn(0.5f, v3), hy = __fmul_rn(0.5f, v4);
        float x1 = __fsub_rn(v0, hx), x2 = __fadd_rn(v0, hx);
        float y1 = __fsub_rn(v1, hy), y2 = __fadd_rn(v1, hy);
        g_box4[b][rank] = make_float4(x1, y1, x2, y2);
        g_area[b][rank] = __fmul_rn(v3, v4);
    }
}

// ================= K2: stage-0 suppression mask (broadcast smem) =============
__global__ void __launch_bounds__(64)
k_mask0() {
    int cb = blockIdx.x, rb = blockIdx.y, b = blockIdx.z;
    if (cb < rb) return;

    __shared__ float4 sb[64];
    __shared__ float  sa[64];
    int t = threadIdx.x;
    sb[t] = g_box4[b][cb * 64 + t];
    sa[t] = g_area[b][cb * 64 + t];
    __syncthreads();

    int i = rb * 64 + t;
    float4 me = g_box4[b][i];
    float  a  = g_area[b][i];
    unsigned long long m = 0;
    int j0 = (cb == rb) ? (t + 1) : 0;               // only j > i suppressed
    for (int jj = j0; jj < 64; jj++) {               // sb[jj]: broadcast, conflict-free
        if (iou_gt(me, a, sb[jj], sa[jj])) m |= (1ull << jj);
    }
    g_mask0[b][(size_t)i * NW1 + cb] = m;
}

// ================= K3: scan stage-0 + fallback + compact + output ============
__global__ void __launch_bounds__(1024)
k_scan_out(float* __restrict__ out) {
    int b = blockIdx.x, tid = threadIdx.x;
    extern __shared__ unsigned char dsm[];
    float4* sbox  = (float4*)dsm;                    // fallback only: 4096*16B
    float*  sarea = (float*)(dsm + KSEL * 16);       // fallback only: 4096*4B

    __shared__ unsigned long long remv[NWORDS];
    __shared__ unsigned long long acc_s[NWORDS];
    __shared__ unsigned long long diag[64];
    __shared__ unsigned long long part[1088];        // stage0 r*17+cw ; fb q*65+c
    __shared__ unsigned long long red[4][16];
    __shared__ int pref[NWORDS];
    __shared__ int s_fb;

    // zero this batch's output slice early (d_out is poisoned); independent work
    float* rbase = out + b * KPOST * 7;
    for (int e = tid; e < KPOST * 7; e += 1024) rbase[e] = 0.0f;
    if (tid < KPOST) {
        out[SC_OFF + b * KPOST + tid] = 0.0f;
        out[LB_OFF + b * KPOST + tid] = 0.0f;
    }

    if (tid < NWORDS) { remv[tid] = 0ull; acc_s[tid] = 0ull; }
    __syncthreads();

    // ---------- stage 0: load 64x16 mask block per word, pipelined ----------
    const unsigned long long* M0 = g_mask0[b];
    int r = tid >> 4, cw = tid & 15;                 // row 0..63, col-word 0..15
    unsigned long long m = M0[(size_t)r * NW1 + cw]; // word-0 block (coalesced)

    for (int w = 0; w < NW1; w++) {
        if (cw == w) diag[r] = m;                    // diagonal for free
        __syncthreads();
        if (tid == 0) {                              // serial greedy decisions
            unsigned long long rem = remv[w], acc = 0ull;
            unsigned long long dn = diag[0];
#pragma unroll
            for (int bit = 0; bit < 64; bit++) {
                unsigned long long d = dn;
                if (bit < 63) dn = diag[bit + 1];
                if (!((rem >> bit) & 1ull)) { acc |= (1ull << bit); rem |= d; }
            }
            acc_s[w] = acc;
        }
        // prefetch next word's block while greedy runs
        unsigned long long mn = 0ull;
        if (w + 1 < NW1) mn = M0[(size_t)((w + 1) * 64 + r) * NW1 + cw];
        __syncthreads();

        unsigned long long acc = acc_s[w];
        part[r * 17 + cw] = ((acc >> r) & 1ull) ? m : 0ull;
        __syncthreads();
        if (tid < 64) {
            int q = tid >> 4, c = tid & 15;
            unsigned long long v = 0ull;
#pragma unroll
            for (int k = 0; k < 16; k++) v |= part[(q * 16 + k) * 17 + c];
            red[q][c] = v;
        }
        __syncthreads();
        if (tid < 16)
            remv[tid] |= red[0][tid] | red[1][tid] | red[2][tid] | red[3][tid];
        __syncthreads();
        m = mn;
    }

    if (tid == 0) {
        int cnt = 0;
        for (int w = 0; w < NW1; w++) cnt += __popcll(acc_s[w]);
        s_fb = (cnt < KPOST);
    }
    __syncthreads();

    // ---------- fallback: full 4096 on-the-fly NMS (never taken normally) ----
    if (s_fb) {
        for (int i = tid; i < KSEL; i += 1024) {
            sbox[i]  = g_box4[b][i];
            sarea[i] = g_area[b][i];
        }
        if (tid < NWORDS) remv[tid] = 0ull;
        __syncthreads();

        int qg = tid >> 6, colw = tid & 63;
        for (int w = 0; w < NWORDS; w++) {
            if (tid < 64) {
                int i = w * 64 + tid;
                float4 A = sbox[i]; float aA = sarea[i];
                unsigned long long d = 0ull;
                for (int j = tid + 1; j < 64; j++) {
                    if (iou_gt(A, aA, sbox[w * 64 + j], sarea[w * 64 + j]))
                        d |= (1ull << j);
                }
                diag[tid] = d;
            }
            __syncthreads();
            if (tid == 0) {
                unsigned long long rem = remv[w], acc = 0ull;
#pragma unroll
                for (int bit = 0; bit < 64; bit++) {
                    if (!((rem >> bit) & 1ull)) { acc |= (1ull << bit); rem |= diag[bit]; }
                }
                acc_s[w] = acc;
            }
            __syncthreads();

            unsigned long long acc = acc_s[w];
            unsigned long long p = 0ull;
            if (colw > w) {
#pragma unroll
                for (int rr = 0; rr < 4; rr++) {
                    int rbit = qg + rr * 16;
                    if ((acc >> rbit) & 1ull) {
                        int i = w * 64 + rbit;
                        float4 A = sbox[i]; float aA = sarea[i];
                        for (int j = 0; j < 64; j++) {
                            if (iou_gt(A, aA, sbox[colw * 64 + j], sarea[colw * 64 + j]))
                                p |= (1ull << j);
                        }
                    }
                }
            }
            part[qg * 65 + colw] = p;
            __syncthreads();
            if (tid < 64) {
                unsigned long long rr2 = remv[tid];
#pragma unroll
                for (int k = 0; k < 16; k++) rr2 |= part[k * 65 + tid];
                remv[tid] = rr2;
            }
            __syncthreads();
        }
    }

    // ---------- compact + output ----------
    if (tid == 0) {
        int s = 0;
        for (int w = 0; w < NWORDS; w++) { pref[w] = s; s += __popcll(acc_s[w]); }
    }
    __syncthreads();

    if (tid < NWORDS) {
        unsigned long long a = acc_s[tid];
        int rank = pref[tid];
        while (a && rank < KPOST) {
            int bit = __ffsll((long long)a) - 1;
            a &= a - 1;
            int i = tid * 64 + bit;
            const float* ro = &g_rois[b][i][0];
            int obase = (b * KPOST + rank) * 7;
#pragma unroll
            for (int c = 0; c < 7; c++) out[obase + c] = ro[c];
            out[SC_OFF + b * KPOST + rank] = g_scores[b][i];
            out[LB_OFF + b * KPOST + rank] = (float)(g_labels[b][i] + 1);
            rank++;
        }
    }
}

// ---------------- launch (3 kernels) ----------------
extern "C" void kernel_launch(void* const* d_in, const int* in_sizes, int n_in,
                              void* d_out, int out_size) {
    const float* boxes = (const float*)d_in[0];
    const float* cls   = (const float*)d_in[1];
    if (n_in >= 2 && in_sizes[0] == BATCH * NPTS * NCLS) {
        boxes = (const float*)d_in[1];
        cls   = (const float*)d_in[0];
    }
    float* out = (float*)d_out;

    const int DSM_SEL  = 16384 + 16384 + CAND_CAP * 8;   // 81920 B
    const int DSM_SCAN = KSEL * 16 + KSEL * 4;           // 81920 B (fallback boxes)

    cudaFuncSetAttribute(k_select,
                         cudaFuncAttributeMaxDynamicSharedMemorySize, DSM_SEL);
    cudaFuncSetAttribute(k_scan_out,
                         cudaFuncAttributeMaxDynamicSharedMemorySize, DSM_SCAN);

    k_select<<<BATCH, 1024, DSM_SEL>>>(boxes, cls);
    k_mask0<<<dim3(NW1, NW1, BATCH), 64>>>();
    k_scan_out<<<BATCH, 1024, DSM_SCAN>>>(out);
}